// round 15
// baseline (speedup 1.0000x reference)
#include <cuda_runtime.h>
#include <math.h>
#include <cstdint>

// ---------------------------------------------------------------------------
// MolecularGNN fused, R14 = R13 + fragment passing:
//  - HT stored with in-group column permutation sigma(c)= c<4?2c:2(c-4)+1,
//    so the agg D-fragment IS the next layer's A-fragment (slot reorder only)
//  - agg on all 8 warps (warp w -> rows 16w; mol w>>1, half w&1)
//  - interior layers: v never touches smem (registers only, tf32-rounded)
//  - last layer: molecule sums from fragments (un-permuted on molP write)
//  - X used only for embeddings (layer-0 A)
// ---------------------------------------------------------------------------

#define MAX_T 524288
#define MAX_LAY 8
#define CAP 32
#define TILE_ROWS 128
#define MPC 4               // molecules per CTA (tensor path)

typedef unsigned long long u64;
typedef unsigned u32;

__device__ unsigned      g_cnt[MAX_T];                  // zero-init (.bss)
__device__ unsigned char g_slots[(size_t)MAX_T * CAP];
__device__ float         g_W [MAX_LAY * 4096];          // GNN W, tf32, [n][k]
__device__ float         g_Wt[MAX_LAY * 4096];          // MLP W, transposed

__device__ __forceinline__ u32 cvt_tf32(float f) {
    u32 u; asm("cvt.rna.tf32.f32 %0, %1;" : "=r"(u) : "f"(f)); return u;
}
__device__ __forceinline__ float cvtf_tf32(float f) {
    return __uint_as_float(cvt_tf32(f));
}
__device__ __forceinline__ int vadr(int r, int q, int wo) {
    return r * 64 + (((q ^ (r & 7)) << 2) + wo);
}
__device__ __forceinline__ u32 smem_u32(const void* p) {
    u32 a; asm("{ .reg .u64 t; cvta.to.shared.u64 t, %1; cvt.u32.u64 %0, t; }"
               : "=r"(a) : "l"(p));
    return a;
}
#define LDSM_X4(r0, r1, r2, r3, addr) \
    asm volatile("ldmatrix.sync.aligned.m8n8.x4.shared.b16 {%0,%1,%2,%3}, [%4];" \
                 : "=r"(r0), "=r"(r1), "=r"(r2), "=r"(r3) : "r"(addr))
#define MMA_TF32(c, a0, a1, a2, a3, b0, b1) \
    asm volatile("mma.sync.aligned.m16n8k8.row.col.f32.tf32.tf32.f32 " \
                 "{%0,%1,%2,%3},{%4,%5,%6,%7},{%8,%9},{%0,%1,%2,%3};" \
                 : "+f"((c)[0]), "+f"((c)[1]), "+f"((c)[2]), "+f"((c)[3]) \
                 : "r"(a0), "r"(a1), "r"(a2), "r"(a3), "r"(b0), "r"(b1))

// ---------------------------------------------------------------------------
__global__ void prep_kernel(const int* __restrict__ src,
                            const int* __restrict__ dst, int E, int S, int EB,
                            const float* __restrict__ Wfp,
                            const float* __restrict__ Wout, int LH) {
    int b = blockIdx.x;
    if (b < EB) {
        int e = b * 256 + threadIdx.x;
        if (e < E) {
            int d = dst[e];
            unsigned idx = atomicAdd(&g_cnt[d], 1u);
            if (idx < CAP) {
                int s = src[e];
                g_slots[(size_t)d * CAP + idx] = (unsigned char)(s - (s / S) * S);
            }
        }
    } else if (b < EB + LH) {
        int l = b - EB;
        const float* Ws = Wfp + l * 4096;
        float* o = g_W + l * 4096;
        for (int i = threadIdx.x; i < 4096; i += blockDim.x)
            o[i] = cvtf_tf32(Ws[i]);
    } else {
        int l = b - EB - LH;
        const float* Ws = Wout + l * 4096;
        float* o = g_Wt + l * 4096;
        for (int i = threadIdx.x; i < 4096; i += blockDim.x) {
            int k = i >> 6, j = i & 63;
            o[i] = Ws[j * 64 + k];
        }
    }
}

// rare-path fallback (degree > CAP), generic kernel only
__device__ __noinline__ float2 gather_fallback(const float* __restrict__ X,
                                               int n, int mb, int S, int E,
                                               const int* __restrict__ esrc,
                                               const int* __restrict__ edst,
                                               int aq, int awo, float2 a) {
    for (int e = 0; e < E; e++)
        if (edst[e] == n) {
            int s = esrc[e];
            int nr = mb + (s - (s / S) * S);
            float2 hh = *(const float2*)&X[vadr(nr, aq, awo)];
            a.x += hh.x; a.y += hh.y;
        }
    return a;
}

// ===========================================================================
// Tensor kernel (S <= 32). smem floats:
//  X 0..8192 | HT 8192..16640 (64x132, col-permuted) | Bw 16640..20736 |
//  Cm 20736..24832 | bias 24832 | molA 25344 | molB 25664 | cnt 25984 |
//  fpx 26112 | slots/molP 26240..27264        total 27264 f = 109056 B
// ===========================================================================
#define SMEM_TC_F 27264

__global__ __launch_bounds__(256, 2)
void gnn_tc_kernel(const int* __restrict__ fp,
                   const float* __restrict__ emb,
                   const float* __restrict__ b_fp,
                   const float* __restrict__ b_out,
                   const float* __restrict__ wprop,
                   const float* __restrict__ bprop,
                   const int* __restrict__ esrc,
                   const int* __restrict__ edst,
                   float* __restrict__ out,
                   int S, int M, int E, int LH, int LO) {
    extern __shared__ float sm[];
    float* X       = sm;
    float* HT      = sm + 8192;
    float* Bw      = sm + 16640;
    float* Cm      = sm + 20736;
    float* bias_sh = sm + 24832;
    float* molA    = sm + 25344;
    float* molB    = sm + 25664;
    unsigned* cnt_sh = (unsigned*)(sm + 25984);
    int*      fpx_sh = (int*)(sm + 26112);
    unsigned char* slot_sh = (unsigned char*)(sm + 26240);  // dead after C build
    float* molP    = sm + 26240;                            // overlays slots

    const int t = threadIdx.x;
    const int warp = t >> 5, lane = t & 31;
    const int molBase = blockIdx.x * MPC;
    const int Ga = min(MPC, M - molBase);
    if (Ga <= 0) return;
    const int atomBase = molBase * S;

    const u32 vbase = smem_u32(X);
    const u32 bbase = smem_u32(Bw);
    const u32 cbase = smem_u32(Cm);
    const u32 htbase = smem_u32(HT);

    const int mi = lane >> 3, li = lane & 7;
    const int rA = warp * 16 + ((mi & 1) << 3) + li;
    const int rB0 = ((mi >> 1) << 3) + li;
    const int qAofs = mi >> 1, qBofs = mi & 1;
    const int c2 = lane * 2;
    const int ec = (lane & 3) * 2;
    // permuted column positions for epilogue store: sigma(c)=c<4?2c:2(c-4)+1
    const int p0 = (ec < 4) ? ec * 2 : (ec - 4) * 2 + 1;
    const int p1 = (ec + 1 < 4) ? (ec + 1) * 2 : (ec - 3) * 2 + 1;

    // ---- prologue: slots/cnt/fpx per padded row; bias; W(0) ----
    for (int r = t; r < TILE_ROWS; r += 256) {
        int m = r >> 5, d = r & 31;
        bool valid = (d < S) && (m < Ga);
        unsigned c = 0;
        if (valid) {
            int ga = atomBase + m * S + d;
            c = g_cnt[ga];
            g_cnt[ga] = 0u;
            fpx_sh[r] = fp[ga] * 16;
            const u64* gs = (const u64*)(g_slots + (size_t)ga * CAP);
            u64* ss = (u64*)(slot_sh + r * CAP);
            ss[0] = gs[0]; ss[1] = gs[1]; ss[2] = gs[2]; ss[3] = gs[3];
        }
        cnt_sh[r] = c;
    }
    if (t < LH * 64) bias_sh[t] = b_fp[t];
    {
        const float4* ws = (const float4*)g_W;
        float4* wd = (float4*)Bw;
        for (int i = t; i < 1024; i += 256) {
            int n = i >> 4, q = i & 15;
            wd[(n << 4) + (q ^ (n & 7))] = ws[i];
        }
    }
    __syncthreads();

    // ---- build C = I + counts (swizzled rows), one thread per row ----
    if (t < TILE_ROWS) {
        int m = t >> 5, d = t & 31;
        float* crow = Cm + m * 1024 + d * 32;
        for (int j = 0; j < 32; j++) crow[j] = 0.f;
        unsigned c = cnt_sh[t];
        if (c <= CAP) {
            const unsigned char* sl = slot_sh + t * CAP;
            for (unsigned e = 0; e < c; e++) {
                int s = sl[e];
                crow[(((s >> 2) ^ (d & 7)) << 2) + (s & 3)] += 1.f;
            }
        } else {                    // unreachable; correctness net
            int n = atomBase + m * S + d;
            for (int e = 0; e < E; e++)
                if (edst[e] == n) {
                    int sg = esrc[e];
                    int s = sg - (sg / S) * S;
                    crow[(((s >> 2) ^ (d & 7)) << 2) + (s & 3)] += 1.f;
                }
        }
        crow[(((d >> 2) ^ (d & 7)) << 2) + (d & 3)] += 1.f;    // +I
    }

    // ---- embeddings (tf32, swizzled; pad rows zero) ----
    {
        const float4* eq = (const float4*)emb;
        for (int idx = t; idx < TILE_ROWS * 16; idx += 256) {
            int r = idx >> 4, q = idx & 15;
            float4 e = make_float4(0.f, 0.f, 0.f, 0.f);
            if (((r & 31) < S) && ((r >> 5) < Ga)) {
                e = eq[fpx_sh[r] + q];
                e.x = cvtf_tf32(e.x); e.y = cvtf_tf32(e.y);
                e.z = cvtf_tf32(e.z); e.w = cvtf_tf32(e.w);
            }
            *(float4*)&X[vadr(r, q, 0)] = e;
        }
    }

    // v fragments (A-operand layout, tf32 bits), produced by agg
    u32 vD[8][4];

    // ---- GNN layers ----
    for (int l = 0; l < LH; l++) {
        __syncthreads();            // Bw(l) ready; HT free; (l=0: X ready)

        // layer GEMM: h = relu(v @ W^T + b); A from X (l=0) or vD regs
        float C[8][4];
#pragma unroll
        for (int nt = 0; nt < 8; nt++)
#pragma unroll
            for (int i = 0; i < 4; i++) C[nt][i] = 0.f;
#pragma unroll
        for (int ks = 0; ks < 8; ks++) {
            u32 a0, a1, a2, a3;
            if (l == 0) {
                u32 ad = vbase + 4u * (u32)vadr(rA, ks * 2 + qAofs, 0);
                LDSM_X4(a0, a1, a2, a3, ad);
            } else {
                // vD slots: {0:(r,k),1:(r,k+4),2:(r+8,k),3:(r+8,k+4)}
                a0 = vD[ks][0]; a1 = vD[ks][2];
                a2 = vD[ks][1]; a3 = vD[ks][3];
            }
            u32 bfr[4][4];
#pragma unroll
            for (int g = 0; g < 4; g++) {
                u32 ad = bbase + 4u * (u32)vadr(g * 16 + rB0, ks * 2 + qBofs, 0);
                LDSM_X4(bfr[g][0], bfr[g][1], bfr[g][2], bfr[g][3], ad);
            }
#pragma unroll
            for (int nt = 0; nt < 8; nt++) {
                int g = nt >> 1, s2 = (nt & 1) * 2;
                MMA_TF32(C[nt], a0, a1, a2, a3, bfr[g][s2], bfr[g][s2 + 1]);
            }
        }

        const bool lastL = (l == LH - 1);
        const int er = warp * 16 + (lane >> 2);
        // epilogue -> HT, column-PERMUTED positions, stride 132
#pragma unroll
        for (int nt = 0; nt < 8; nt++) {
            int c0 = nt * 8 + ec;
            float2 bb = *(const float2*)&bias_sh[l * 64 + c0];
            HT[(nt * 8 + p0) * 132 + er]     = fmaxf(C[nt][0] + bb.x, 0.f);
            HT[(nt * 8 + p1) * 132 + er]     = fmaxf(C[nt][1] + bb.y, 0.f);
            HT[(nt * 8 + p0) * 132 + er + 8] = fmaxf(C[nt][2] + bb.x, 0.f);
            HT[(nt * 8 + p1) * 132 + er + 8] = fmaxf(C[nt][3] + bb.y, 0.f);
        }
        __syncthreads();            // HT ready

        // agg GEMM on all 8 warps: warp w -> rows 16w (mol m=w>>1, half mt)
        {
            const int m = warp >> 1, mt = warp & 1;
            float D[8][4];
#pragma unroll
            for (int nt = 0; nt < 8; nt++)
#pragma unroll
                for (int i = 0; i < 4; i++) D[nt][i] = 0.f;
            if (m < Ga) {
#pragma unroll
                for (int ks = 0; ks < 4; ks++) {
                    u32 af[4];
                    {
                        int row = mt * 16 + ((mi & 1) << 3) + li;
                        int q = ks * 2 + qAofs;
                        u32 ad = cbase + 4u * (u32)(m * 1024 + row * 32
                                   + ((q ^ (row & 7)) << 2));
                        LDSM_X4(af[0], af[1], af[2], af[3], ad);
                    }
                    u32 bf[4][4];
#pragma unroll
                    for (int g = 0; g < 4; g++) {
                        int n = g * 16 + rB0;
                        u32 ad = htbase + 4u * (u32)(n * 132 + m * 32
                                   + ks * 8 + qBofs * 4);
                        LDSM_X4(bf[g][0], bf[g][1], bf[g][2], bf[g][3], ad);
                    }
#pragma unroll
                    for (int nt = 0; nt < 8; nt++) {
                        int g = nt >> 1, s2 = (nt & 1) * 2;
                        MMA_TF32(D[nt], af[0], af[1], af[2], af[3],
                                 bf[g][s2], bf[g][s2 + 1]);
                    }
                }
                // norms: row r (slots 0,1) and row r+8 (slots 2,3)
                float iv[2];
#pragma unroll
                for (int h = 0; h < 2; h++) {
                    float ssq = 0.f;
#pragma unroll
                    for (int nt = 0; nt < 8; nt++)
                        ssq += D[nt][2 * h] * D[nt][2 * h]
                             + D[nt][2 * h + 1] * D[nt][2 * h + 1];
                    ssq += __shfl_xor_sync(0xffffffffu, ssq, 1);
                    ssq += __shfl_xor_sync(0xffffffffu, ssq, 2);
                    iv[h] = rsqrtf(fmaxf(ssq, 1e-24f));
                }
                if (!lastL) {
                    // v fragments for next layer (tf32-rounded)
#pragma unroll
                    for (int nt = 0; nt < 8; nt++) {
                        vD[nt][0] = cvt_tf32(D[nt][0] * iv[0]);
                        vD[nt][1] = cvt_tf32(D[nt][1] * iv[0]);
                        vD[nt][2] = cvt_tf32(D[nt][2] * iv[1]);
                        vD[nt][3] = cvt_tf32(D[nt][3] * iv[1]);
                    }
                } else {
                    // molecule partial sums from fragments (exclude pads)
                    int lr0 = mt * 16 + (lane >> 2);        // local row, h=0
                    float w0 = (lr0 < S) ? iv[0] : 0.f;
                    float w1 = (lr0 + 8 < S) ? iv[1] : 0.f;
                    float ps[8][2];
#pragma unroll
                    for (int nt = 0; nt < 8; nt++) {
                        ps[nt][0] = D[nt][0] * w0 + D[nt][2] * w1;  // col j
                        ps[nt][1] = D[nt][1] * w0 + D[nt][3] * w1;  // col j+4
                    }
#pragma unroll
                    for (int o = 4; o <= 16; o <<= 1)
#pragma unroll
                        for (int nt = 0; nt < 8; nt++) {
                            ps[nt][0] += __shfl_xor_sync(0xffffffffu, ps[nt][0], o);
                            ps[nt][1] += __shfl_xor_sync(0xffffffffu, ps[nt][1], o);
                        }
                    if ((lane >> 2) == 0) {     // lanes 0-3: j = lane
#pragma unroll
                        for (int nt = 0; nt < 8; nt++) {
                            molP[warp * 64 + nt * 8 + lane]     = ps[nt][0];
                            molP[warp * 64 + nt * 8 + lane + 4] = ps[nt][1];
                        }
                    }
                }
            }
        }
        // stage next weights (all threads; Bw untouched by agg)
        if (!lastL) {
            const float4* ws = (const float4*)(g_W + (l + 1) * 4096);
            float4* wd = (float4*)Bw;
            for (int i = t; i < 1024; i += 256) {
                int n = i >> 4, q = i & 15;
                wd[(n << 4) + (q ^ (n & 7))] = ws[i];
            }
        } else {
            const float4* ws = (const float4*)g_Wt;
            float4* wd = (float4*)Bw;
            for (int i = t; i < 1024; i += 256) wd[i] = ws[i];
        }
    }
    __syncthreads();    // molP ready, Bw = MLP layer 0

    // ---- combine molecule halves ----
    if (warp < Ga) {
        float2 a = *(const float2*)&molP[(2 * warp) * 64 + c2];
        float2 b = *(const float2*)&molP[(2 * warp + 1) * 64 + c2];
        a.x += b.x; a.y += b.y;
        *(float2*)&molA[warp * 64 + c2] = a;
    }
    __syncthreads();

    // ---- output MLP (warp per molecule) ----
    float* cur = molA;
    float* nxt = molB;
    for (int l = 0; l < LO; l++) {
        if (l > 0) {
            __syncthreads();
            const float4* ws = (const float4*)(g_Wt + l * 4096);
            float4* wd = (float4*)Bw;
            for (int i = t; i < 1024; i += 256) wd[i] = ws[i];
            __syncthreads();
        }
        if (warp < Ga) {
            float2 a = *(const float2*)&b_out[l * 64 + c2];
#pragma unroll 8
            for (int k = 0; k < 64; k++) {
                float cc = cur[warp * 64 + k];
                float2 w2 = *(const float2*)&Bw[k * 64 + c2];
                a.x = fmaf(cc, w2.x, a.x); a.y = fmaf(cc, w2.y, a.y);
            }
            a.x = fmaxf(a.x, 0.f); a.y = fmaxf(a.y, 0.f);
            *(float2*)&nxt[warp * 64 + c2] = a;
        }
        float* tmp = cur; cur = nxt; nxt = tmp;
        __syncthreads();
    }

    // ---- final dot ----
    if (warp < Ga) {
        float s = cur[warp * 64 + lane] * wprop[lane]
                + cur[warp * 64 + 32 + lane] * wprop[32 + lane];
#pragma unroll
        for (int o = 16; o; o >>= 1) s += __shfl_xor_sync(0xffffffffu, s, o);
        if (lane == 0) out[molBase + warp] = s + bprop[0];
    }
}

// ===========================================================================
// Generic fallback (R7 structure) for S > 32
// ===========================================================================
#define SMEM_F_GEN 22304

__global__ __launch_bounds__(256, 2)
void gnn_generic_kernel(const int* __restrict__ fp,
                        const float* __restrict__ emb,
                        const float* __restrict__ b_fp,
                        const float* __restrict__ b_out,
                        const float* __restrict__ wprop,
                        const float* __restrict__ bprop,
                        const int* __restrict__ esrc,
                        const int* __restrict__ edst,
                        float* __restrict__ out,
                        int S, int G, int M, int E, int LH, int LO) {
    extern __shared__ float sm[];
    float* A      = sm;
    float* H      = sm + 8192;
    float* Bw     = sm + 16384;
    float* bias_sh = sm + 20480;
    unsigned* cnt_sh = (unsigned*)(sm + 20992);
    int*      fpx_sh = (int*)(sm + 21120);
    unsigned char* slot_sh = (unsigned char*)(sm + 21248);
    unsigned char* mb_sh   = (unsigned char*)(sm + 22272);

    const int t = threadIdx.x;
    const int warp = t >> 5, lane = t & 31;
    const int molBase = blockIdx.x * G;
    const int Ga = min(G, M - molBase);
    if (Ga <= 0) return;
    const int GA = Ga * S;
    const int atomBase = molBase * S;

    const u32 vbase = smem_u32(A);
    const u32 bbase = smem_u32(Bw);
    const int mi = lane >> 3, li = lane & 7;
    const int rA = warp * 16 + ((mi & 1) << 3) + li;
    const int rB0 = ((mi >> 1) << 3) + li;
    const int qAofs = mi >> 1, qBofs = mi & 1;

    {
        const u64* gs = (const u64*)(g_slots + (size_t)atomBase * CAP);
        u64* ss = (u64*)slot_sh;
        const int nQ = (GA * CAP) >> 3;
        for (int i = t; i < nQ; i += 256) ss[i] = gs[i];
        for (int r = t; r < GA; r += 256) {
            cnt_sh[r] = g_cnt[atomBase + r];
            g_cnt[atomBase + r] = 0u;
            fpx_sh[r] = fp[atomBase + r] * 16;
        }
        for (int r = t; r < TILE_ROWS; r += 256)
            mb_sh[r] = (unsigned char)((r / S) * S);
        if (t < LH * 64) bias_sh[t] = b_fp[t];
        const float4* ws = (const float4*)g_W;
        float4* wd = (float4*)Bw;
        for (int i = t; i < 1024; i += 256) {
            int n = i >> 4, q = i & 15;
            wd[(n << 4) + (q ^ (n & 7))] = ws[i];
        }
    }
    __syncthreads();

    {
        const float4* eq = (const float4*)emb;
        for (int idx = t; idx < GA * 16; idx += 256) {
            int r = idx >> 4, q = idx & 15;
            float4 e = eq[fpx_sh[r] + q];
            e.x = cvtf_tf32(e.x); e.y = cvtf_tf32(e.y);
            e.z = cvtf_tf32(e.z); e.w = cvtf_tf32(e.w);
            *(float4*)&A[vadr(r, q, 0)] = e;
        }
        const float4 z = make_float4(0.f, 0.f, 0.f, 0.f);
        for (int idx = GA * 16 + t; idx < TILE_ROWS * 16; idx += 256)
            *(float4*)&A[vadr(idx >> 4, idx & 15, 0)] = z;
    }

    for (int l = 0; l < LH; l++) {
        __syncthreads();
        float C[8][4];
#pragma unroll
        for (int nt = 0; nt < 8; nt++)
#pragma unroll
            for (int i = 0; i < 4; i++) C[nt][i] = 0.f;
#pragma unroll
        for (int ks = 0; ks < 8; ks++) {
            u32 a0, a1, a2, a3;
            {
                u32 ad = vbase + 4u * (u32)vadr(rA, ks * 2 + qAofs, 0);
                LDSM_X4(a0, a1, a2, a3, ad);
            }
            u32 bfr[4][4];
#pragma unroll
            for (int g = 0; g < 4; g++) {
                u32 ad = bbase + 4u * (u32)vadr(g * 16 + rB0, ks * 2 + qBofs, 0);
                LDSM_X4(bfr[g][0], bfr[g][1], bfr[g][2], bfr[g][3], ad);
            }
#pragma unroll
            for (int nt = 0; nt < 8; nt++) {
                int g = nt >> 1, s2 = (nt & 1) * 2;
                MMA_TF32(C[nt], a0, a1, a2, a3, bfr[g][s2], bfr[g][s2 + 1]);
            }
        }
        {
            int er = warp * 16 + (lane >> 2);
            int ec = (lane & 3) * 2;
#pragma unroll
            for (int nt = 0; nt < 8; nt++) {
                int col = nt * 8 + ec;
                float2 bb = *(const float2*)&bias_sh[l * 64 + col];
                float2 h0, h1;
                h0.x = fmaxf(C[nt][0] + bb.x, 0.f);
                h0.y = fmaxf(C[nt][1] + bb.y, 0.f);
                h1.x = fmaxf(C[nt][2] + bb.x, 0.f);
                h1.y = fmaxf(C[nt][3] + bb.y, 0.f);
                *(float2*)&H[vadr(er,     col >> 2, col & 3)] = h0;
                *(float2*)&H[vadr(er + 8, col >> 2, col & 3)] = h1;
            }
        }
        __syncthreads();

        const bool lastL = (l == LH - 1);
        const int aq = lane >> 1, awo = (lane & 1) * 2, c2 = lane * 2;
        for (int r = warp; r < GA; r += 8) {
            unsigned c = cnt_sh[r];
            int mb = mb_sh[r];
            float2 a = *(const float2*)&H[vadr(r, aq, awo)];
            if (c <= CAP) {
                const unsigned char* sl = slot_sh + r * CAP;
                float2 s1 = make_float2(0.f, 0.f);
                unsigned e = 0;
                for (; e + 2 <= c; e += 2) {
                    int n0 = mb + sl[e], n1 = mb + sl[e + 1];
                    float2 h0 = *(const float2*)&H[vadr(n0, aq, awo)];
                    float2 h1 = *(const float2*)&H[vadr(n1, aq, awo)];
                    a.x += h0.x;  a.y += h0.y;
                    s1.x += h1.x; s1.y += h1.y;
                }
                if (e < c) {
                    int n0 = mb + sl[e];
                    float2 h0 = *(const float2*)&H[vadr(n0, aq, awo)];
                    a.x += h0.x; a.y += h0.y;
                }
                a.x += s1.x; a.y += s1.y;
            } else {
                a = gather_fallback(H, atomBase + r, mb, S, E, esrc, edst,
                                    aq, awo, a);
            }
            float ss = a.x * a.x + a.y * a.y;
#pragma unroll
            for (int o = 16; o; o >>= 1) ss += __shfl_xor_sync(0xffffffffu, ss, o);
            float iv = rsqrtf(fmaxf(ss, 1e-24f));
            a.x *= iv; a.y *= iv;
            if (!lastL) {
                float2 w1; w1.x = cvtf_tf32(a.x); w1.y = cvtf_tf32(a.y);
                *(float2*)&A[vadr(r, aq, awo)] = w1;
            } else {
                *(float2*)&A[r * 64 + c2] = a;
            }
        }
        if (l + 1 < LH) {
            const float4* ws = (const float4*)(g_W + (l + 1) * 4096);
            float4* wd = (float4*)Bw;
            for (int i = t; i < 1024; i += 256) {
                int n = i >> 4, q = i & 15;
                wd[(n << 4) + (q ^ (n & 7))] = ws[i];
            }
        } else {
            const float4* ws = (const float4*)g_Wt;
            float4* wd = (float4*)Bw;
            for (int i = t; i < 1024; i += 256) wd[i] = ws[i];
        }
    }
    __syncthreads();

    const int c2 = lane * 2;
    for (int m = warp; m < Ga; m += 8) {
        float2 s = make_float2(0.f, 0.f);
        for (int i = 0; i < S; i++) {
            float2 x = *(const float2*)&A[(m * S + i) * 64 + c2];
            s.x += x.x; s.y += x.y;
        }
        *(float2*)&H[m * 64 + c2] = s;
    }

    float* cur = H;
    float* nxt = A;
    for (int l = 0; l < LO; l++) {
        if (l > 0) {
            __syncthreads();
            const float4* ws = (const float4*)(g_Wt + l * 4096);
            float4* wd = (float4*)Bw;
            for (int i = t; i < 1024; i += 256) wd[i] = ws[i];
        }
        __syncthreads();
        for (int m = warp; m < Ga; m += 8) {
            float2 a = *(const float2*)&b_out[l * 64 + c2];
#pragma unroll 8
            for (int k = 0; k < 64; k++) {
                float cc = cur[m * 64 + k];
                float2 w2 = *(const float2*)&Bw[k * 64 + c2];
                a.x = fmaf(cc, w2.x, a.x); a.y = fmaf(cc, w2.y, a.y);
            }
            a.x = fmaxf(a.x, 0.f); a.y = fmaxf(a.y, 0.f);
            *(float2*)&nxt[m * 64 + c2] = a;
        }
        float* tmp = cur; cur = nxt; nxt = tmp;
    }
    __syncthreads();

    for (int m = warp; m < Ga; m += 8) {
        float s = cur[m * 64 + lane] * wprop[lane]
                + cur[m * 64 + 32 + lane] * wprop[32 + lane];
#pragma unroll
        for (int o = 16; o; o >>= 1) s += __shfl_xor_sync(0xffffffffu, s, o);
        if (lane == 0) out[molBase + m] = s + bprop[0];
    }
}

// ---------------------------------------------------------------------------

extern "C" void kernel_launch(void* const* d_in, const int* in_sizes, int n_in,
                              void* d_out, int out_size) {
    const float* emb    = (const float*)d_in[0];
    const float* W_fp   = (const float*)d_in[1];
    const float* b_fp   = (const float*)d_in[2];
    const float* W_out  = (const float*)d_in[3];
    const float* b_out  = (const float*)d_in[4];
    const float* W_prop = (const float*)d_in[5];
    const float* b_prop = (const float*)d_in[6];
    const int*   fp     = (const int*)d_in[7];
    const int*   esrc   = (const int*)d_in[8];
    const int*   edst   = (const int*)d_in[9];

    float* out = (float*)d_out;

    const int M  = out_size;
    const int T  = in_sizes[7];
    const int E  = in_sizes[8];
    const int LH = in_sizes[2] / 64;
    const int LO = in_sizes[4] / 64;
    const int S  = T / M;

    const int EB = (E + 255) / 256;
    prep_kernel<<<EB + LH + LO, 256>>>(esrc, edst, E, S, EB, W_fp, W_out, LH);

    if (S <= 32 && LH <= MAX_LAY && LO <= MAX_LAY) {
        const int smemBytes = SMEM_TC_F * 4;        // 109056 B
        cudaFuncSetAttribute(gnn_tc_kernel,
                             cudaFuncAttributeMaxDynamicSharedMemorySize, smemBytes);
        const int nBlocks = (M + MPC - 1) / MPC;
        gnn_tc_kernel<<<nBlocks, 256, smemBytes>>>(
            fp, emb, b_fp, b_out, W_prop, b_prop, esrc, edst, out,
            S, M, E, LH, LO);
    } else {
        int G = TILE_ROWS / S;
        if (G < 1) G = 1;
        const int smemBytes = SMEM_F_GEN * 4;
        cudaFuncSetAttribute(gnn_generic_kernel,
                             cudaFuncAttributeMaxDynamicSharedMemorySize, smemBytes);
        const int nBlocks = (M + G - 1) / G;
        gnn_generic_kernel<<<nBlocks, 256, smemBytes>>>(
            fp, emb, b_fp, b_out, W_prop, b_prop, esrc, edst, out,
            S, G, M, E, LH, LO);
    }
}

// round 16
// speedup vs baseline: 1.0528x; 1.0528x over previous
#include <cuda_runtime.h>
#include <math.h>
#include <cstdint>

// ---------------------------------------------------------------------------
// MolecularGNN fused, R15 = R13 (best, 371us) + 8-warp MLP tail:
//  warp w handles molecule w>>1, column half (w&1)*32 + lane (1 col/lane).
//  All GNN-layer structure identical to R13 (R14 fragment passing reverted:
//  it doubled B-ldsm and serialized weight staging -> regression).
// ---------------------------------------------------------------------------

#define MAX_T 524288
#define MAX_LAY 8
#define CAP 32
#define TILE_ROWS 128
#define MPC 4               // molecules per CTA (tensor path)

typedef unsigned long long u64;
typedef unsigned u32;

__device__ unsigned      g_cnt[MAX_T];                  // zero-init (.bss)
__device__ unsigned char g_slots[(size_t)MAX_T * CAP];
__device__ float         g_W [MAX_LAY * 4096];          // GNN W, tf32, [n][k]
__device__ float         g_Wt[MAX_LAY * 4096];          // MLP W, transposed

__device__ __forceinline__ u32 cvt_tf32(float f) {
    u32 u; asm("cvt.rna.tf32.f32 %0, %1;" : "=r"(u) : "f"(f)); return u;
}
__device__ __forceinline__ float cvtf_tf32(float f) {
    return __uint_as_float(cvt_tf32(f));
}
__device__ __forceinline__ int vadr(int r, int q, int wo) {
    return r * 64 + (((q ^ (r & 7)) << 2) + wo);
}
__device__ __forceinline__ u32 smem_u32(const void* p) {
    u32 a; asm("{ .reg .u64 t; cvta.to.shared.u64 t, %1; cvt.u32.u64 %0, t; }"
               : "=r"(a) : "l"(p));
    return a;
}
#define LDSM_X4(r0, r1, r2, r3, addr) \
    asm volatile("ldmatrix.sync.aligned.m8n8.x4.shared.b16 {%0,%1,%2,%3}, [%4];" \
                 : "=r"(r0), "=r"(r1), "=r"(r2), "=r"(r3) : "r"(addr))
#define MMA_TF32(c, a0, a1, a2, a3, b0, b1) \
    asm volatile("mma.sync.aligned.m16n8k8.row.col.f32.tf32.tf32.f32 " \
                 "{%0,%1,%2,%3},{%4,%5,%6,%7},{%8,%9},{%0,%1,%2,%3};" \
                 : "+f"((c)[0]), "+f"((c)[1]), "+f"((c)[2]), "+f"((c)[3]) \
                 : "r"(a0), "r"(a1), "r"(a2), "r"(a3), "r"(b0), "r"(b1))

// ---------------------------------------------------------------------------
__global__ void prep_kernel(const int* __restrict__ src,
                            const int* __restrict__ dst, int E, int S, int EB,
                            const float* __restrict__ Wfp,
                            const float* __restrict__ Wout, int LH) {
    int b = blockIdx.x;
    if (b < EB) {
        int e = b * 256 + threadIdx.x;
        if (e < E) {
            int d = dst[e];
            unsigned idx = atomicAdd(&g_cnt[d], 1u);
            if (idx < CAP) {
                int s = src[e];
                g_slots[(size_t)d * CAP + idx] = (unsigned char)(s - (s / S) * S);
            }
        }
    } else if (b < EB + LH) {
        int l = b - EB;
        const float* Ws = Wfp + l * 4096;
        float* o = g_W + l * 4096;
        for (int i = threadIdx.x; i < 4096; i += blockDim.x)
            o[i] = cvtf_tf32(Ws[i]);
    } else {
        int l = b - EB - LH;
        const float* Ws = Wout + l * 4096;
        float* o = g_Wt + l * 4096;
        for (int i = threadIdx.x; i < 4096; i += blockDim.x) {
            int k = i >> 6, j = i & 63;
            o[i] = Ws[j * 64 + k];
        }
    }
}

// rare-path fallback (degree > CAP), generic kernel only
__device__ __noinline__ float2 gather_fallback(const float* __restrict__ X,
                                               int n, int mb, int S, int E,
                                               const int* __restrict__ esrc,
                                               const int* __restrict__ edst,
                                               int aq, int awo, float2 a) {
    for (int e = 0; e < E; e++)
        if (edst[e] == n) {
            int s = esrc[e];
            int nr = mb + (s - (s / S) * S);
            float2 hh = *(const float2*)&X[vadr(nr, aq, awo)];
            a.x += hh.x; a.y += hh.y;
        }
    return a;
}

// ===========================================================================
// Tensor-agg kernel (S <= 32). smem floats:
//  X 0..8192 | HT 8192..16640 (64x132) | Bw 16640..20736 | Cm 20736..24832 |
//  bias 24832 | molA 25344 | molB 25664 | cnt 25984 | fpx 26112 |
//  slots 26240..27264 (4096B)      total 27264 f = 109056 B
// ===========================================================================
#define SMEM_TC_F 27264

__global__ __launch_bounds__(256, 2)
void gnn_tc_kernel(const int* __restrict__ fp,
                   const float* __restrict__ emb,
                   const float* __restrict__ b_fp,
                   const float* __restrict__ b_out,
                   const float* __restrict__ wprop,
                   const float* __restrict__ bprop,
                   const int* __restrict__ esrc,
                   const int* __restrict__ edst,
                   float* __restrict__ out,
                   int S, int M, int E, int LH, int LO) {
    extern __shared__ float sm[];
    float* X       = sm;
    float* HT      = sm + 8192;
    float* Bw      = sm + 16640;
    float* Cm      = sm + 20736;
    float* bias_sh = sm + 24832;
    float* molA    = sm + 25344;
    float* molB    = sm + 25664;
    unsigned* cnt_sh = (unsigned*)(sm + 25984);
    int*      fpx_sh = (int*)(sm + 26112);
    unsigned char* slot_sh = (unsigned char*)(sm + 26240);

    const int t = threadIdx.x;
    const int warp = t >> 5, lane = t & 31;
    const int molBase = blockIdx.x * MPC;
    const int Ga = min(MPC, M - molBase);
    if (Ga <= 0) return;
    const int atomBase = molBase * S;

    const u32 vbase = smem_u32(X);
    const u32 bbase = smem_u32(Bw);
    const u32 cbase = smem_u32(Cm);
    const u32 htbase = smem_u32(HT);

    const int mi = lane >> 3, li = lane & 7;
    const int rA = warp * 16 + ((mi & 1) << 3) + li;
    const int rB0 = ((mi >> 1) << 3) + li;
    const int qAofs = mi >> 1, qBofs = mi & 1;
    const int aq = lane >> 1, awo = (lane & 1) * 2, c2 = lane * 2;

    // ---- prologue: slots/cnt/fpx per padded row; bias; W(0) ----
    for (int r = t; r < TILE_ROWS; r += 256) {
        int m = r >> 5, d = r & 31;
        bool valid = (d < S) && (m < Ga);
        unsigned c = 0;
        if (valid) {
            int ga = atomBase + m * S + d;
            c = g_cnt[ga];
            g_cnt[ga] = 0u;
            fpx_sh[r] = fp[ga] * 16;
            const u64* gs = (const u64*)(g_slots + (size_t)ga * CAP);
            u64* ss = (u64*)(slot_sh + r * CAP);
            ss[0] = gs[0]; ss[1] = gs[1]; ss[2] = gs[2]; ss[3] = gs[3];
        }
        cnt_sh[r] = c;
    }
    if (t < LH * 64) bias_sh[t] = b_fp[t];
    {
        const float4* ws = (const float4*)g_W;
        float4* wd = (float4*)Bw;
        for (int i = t; i < 1024; i += 256) {
            int n = i >> 4, q = i & 15;
            wd[(n << 4) + (q ^ (n & 7))] = ws[i];
        }
    }
    __syncthreads();

    // ---- build C = I + counts (swizzled rows), one thread per row ----
    if (t < TILE_ROWS) {
        int m = t >> 5, d = t & 31;
        float* crow = Cm + m * 1024 + d * 32;
        for (int j = 0; j < 32; j++) crow[j] = 0.f;
        unsigned c = cnt_sh[t];
        if (c <= CAP) {
            const unsigned char* sl = slot_sh + t * CAP;
            for (unsigned e = 0; e < c; e++) {
                int s = sl[e];
                crow[(((s >> 2) ^ (d & 7)) << 2) + (s & 3)] += 1.f;
            }
        } else {                    // unreachable; correctness net
            int n = atomBase + m * S + d;
            for (int e = 0; e < E; e++)
                if (edst[e] == n) {
                    int sg = esrc[e];
                    int s = sg - (sg / S) * S;
                    crow[(((s >> 2) ^ (d & 7)) << 2) + (s & 3)] += 1.f;
                }
        }
        crow[(((d >> 2) ^ (d & 7)) << 2) + (d & 3)] += 1.f;    // +I
    }

    // ---- embeddings (tf32, swizzled; pad rows zero) ----
    {
        const float4* eq = (const float4*)emb;
        for (int idx = t; idx < TILE_ROWS * 16; idx += 256) {
            int r = idx >> 4, q = idx & 15;
            float4 e = make_float4(0.f, 0.f, 0.f, 0.f);
            if (((r & 31) < S) && ((r >> 5) < Ga)) {
                e = eq[fpx_sh[r] + q];
                e.x = cvtf_tf32(e.x); e.y = cvtf_tf32(e.y);
                e.z = cvtf_tf32(e.z); e.w = cvtf_tf32(e.w);
            }
            *(float4*)&X[vadr(r, q, 0)] = e;
        }
    }

    // ---- GNN layers ----
    for (int l = 0; l < LH; l++) {
        __syncthreads();            // X(v) + Bw(l) + Cm ready

        // layer GEMM: h = relu(v @ W^T + b)
        float C[8][4];
#pragma unroll
        for (int nt = 0; nt < 8; nt++)
#pragma unroll
            for (int i = 0; i < 4; i++) C[nt][i] = 0.f;
#pragma unroll
        for (int ks = 0; ks < 8; ks++) {
            u32 a0, a1, a2, a3;
            {
                u32 ad = vbase + 4u * (u32)vadr(rA, ks * 2 + qAofs, 0);
                LDSM_X4(a0, a1, a2, a3, ad);
            }
            u32 bfr[4][4];
#pragma unroll
            for (int g = 0; g < 4; g++) {
                u32 ad = bbase + 4u * (u32)vadr(g * 16 + rB0, ks * 2 + qBofs, 0);
                LDSM_X4(bfr[g][0], bfr[g][1], bfr[g][2], bfr[g][3], ad);
            }
#pragma unroll
            for (int nt = 0; nt < 8; nt++) {
                int g = nt >> 1, s2 = (nt & 1) * 2;
                MMA_TF32(C[nt], a0, a1, a2, a3, bfr[g][s2], bfr[g][s2 + 1]);
            }
        }

        const bool lastL = (l == LH - 1);
        const int er = warp * 16 + (lane >> 2);
        const int ec = (lane & 3) * 2;
        // epilogue -> H^T [col][atom], stride 132 (conflict-free), all layers
#pragma unroll
        for (int nt = 0; nt < 8; nt++) {
            int col = nt * 8 + ec;
            float2 bb = *(const float2*)&bias_sh[l * 64 + col];
            HT[col * 132 + er]           = fmaxf(C[nt][0] + bb.x, 0.f);
            HT[(col + 1) * 132 + er]     = fmaxf(C[nt][1] + bb.y, 0.f);
            HT[col * 132 + er + 8]       = fmaxf(C[nt][2] + bb.x, 0.f);
            HT[(col + 1) * 132 + er + 8] = fmaxf(C[nt][3] + bb.y, 0.f);
        }
        __syncthreads();            // H^T ready

        if (warp < 4) {
            // agg GEMM: D[32,64] = C_m[32,32] @ H_m[32,64]  (mol = warp)
            const int m = warp;
            if (m < Ga) {
                float D[2][8][4];
#pragma unroll
                for (int mt = 0; mt < 2; mt++)
#pragma unroll
                    for (int nt = 0; nt < 8; nt++)
#pragma unroll
                        for (int i = 0; i < 4; i++) D[mt][nt][i] = 0.f;
#pragma unroll
                for (int ks = 0; ks < 4; ks++) {
                    u32 af[2][4];
#pragma unroll
                    for (int mt = 0; mt < 2; mt++) {
                        int row = mt * 16 + ((mi & 1) << 3) + li;
                        int q = ks * 2 + qAofs;
                        u32 ad = cbase + 4u * (u32)(m * 1024 + row * 32
                                   + ((q ^ (row & 7)) << 2));
                        LDSM_X4(af[mt][0], af[mt][1], af[mt][2], af[mt][3], ad);
                    }
                    u32 bf[4][4];
#pragma unroll
                    for (int g = 0; g < 4; g++) {
                        int n = g * 16 + rB0;
                        u32 ad = htbase + 4u * (u32)(n * 132 + m * 32
                                   + ks * 8 + qBofs * 4);
                        LDSM_X4(bf[g][0], bf[g][1], bf[g][2], bf[g][3], ad);
                    }
#pragma unroll
                    for (int mt = 0; mt < 2; mt++)
#pragma unroll
                        for (int nt = 0; nt < 8; nt++) {
                            int g = nt >> 1, s2 = (nt & 1) * 2;
                            MMA_TF32(D[mt][nt], af[mt][0], af[mt][1],
                                     af[mt][2], af[mt][3],
                                     bf[g][s2], bf[g][s2 + 1]);
                        }
                }
                // norm in-fragment + write v to X (swizzled)
                // interior layers: tf32-round for next MMA; last: full fp32
#pragma unroll
                for (int mt = 0; mt < 2; mt++)
#pragma unroll
                    for (int h = 0; h < 2; h++) {
                        float ssq = 0.f;
#pragma unroll
                        for (int nt = 0; nt < 8; nt++)
                            ssq += D[mt][nt][2 * h] * D[mt][nt][2 * h]
                                 + D[mt][nt][2 * h + 1] * D[mt][nt][2 * h + 1];
                        ssq += __shfl_xor_sync(0xffffffffu, ssq, 1);
                        ssq += __shfl_xor_sync(0xffffffffu, ssq, 2);
                        float iv = rsqrtf(fmaxf(ssq, 1e-24f));
                        int r = m * 32 + mt * 16 + h * 8 + (lane >> 2);
#pragma unroll
                        for (int nt = 0; nt < 8; nt++) {
                            int col = nt * 8 + ec;
                            float2 w;
                            if (!lastL) {
                                w.x = cvtf_tf32(D[mt][nt][2 * h] * iv);
                                w.y = cvtf_tf32(D[mt][nt][2 * h + 1] * iv);
                            } else {
                                w.x = D[mt][nt][2 * h] * iv;
                                w.y = D[mt][nt][2 * h + 1] * iv;
                            }
                            *(float2*)&X[vadr(r, col >> 2, col & 3)] = w;
                        }
                    }
            }
        } else {
            // warps 4-7: stage next weights
            if (!lastL) {           // next GNN layer (swizzled)
                const float4* ws = (const float4*)(g_W + (l + 1) * 4096);
                float4* wd = (float4*)Bw;
                for (int i = t - 128; i < 1024; i += 128) {
                    int n = i >> 4, q = i & 15;
                    wd[(n << 4) + (q ^ (n & 7))] = ws[i];
                }
            } else {                // MLP layer 0 (plain)
                const float4* ws = (const float4*)g_Wt;
                float4* wd = (float4*)Bw;
                for (int i = t - 128; i < 1024; i += 128) wd[i] = ws[i];
            }
        }
    }
    __syncthreads();    // X = v (swizzled fp32), Bw = MLP layer 0

    // ---- molecule sums (read swizzled) ----
    if (warp < Ga) {
        float2 s = make_float2(0.f, 0.f);
        for (int i = 0; i < S; i++) {
            float2 x = *(const float2*)&X[vadr(warp * 32 + i, aq, awo)];
            s.x += x.x; s.y += x.y;
        }
        *(float2*)&molA[warp * 64 + c2] = s;
    }
    __syncthreads();

    // ---- output MLP: 8 warps, warp w -> molecule w>>1, col (w&1)*32+lane ----
    float* cur = molA;
    float* nxt = molB;
    const int mlpM = warp >> 1;
    const int mlpC = (warp & 1) * 32 + lane;
    for (int l = 0; l < LO; l++) {
        if (l > 0) {
            __syncthreads();
            const float4* ws = (const float4*)(g_Wt + l * 4096);
            float4* wd = (float4*)Bw;
            for (int i = t; i < 1024; i += 256) wd[i] = ws[i];
            __syncthreads();
        }
        if (mlpM < Ga) {
            float a = b_out[l * 64 + mlpC];
#pragma unroll 8
            for (int k = 0; k < 64; k++)
                a = fmaf(cur[mlpM * 64 + k], Bw[k * 64 + mlpC], a);
            nxt[mlpM * 64 + mlpC] = fmaxf(a, 0.f);
        }
        float* tmp = cur; cur = nxt; nxt = tmp;
        __syncthreads();
    }

    // ---- final dot ----
    if (warp < Ga) {
        float s = cur[warp * 64 + lane] * wprop[lane]
                + cur[warp * 64 + 32 + lane] * wprop[32 + lane];
#pragma unroll
        for (int o = 16; o; o >>= 1) s += __shfl_xor_sync(0xffffffffu, s, o);
        if (lane == 0) out[molBase + warp] = s + bprop[0];
    }
}

// ===========================================================================
// Generic fallback (R7 structure) for S > 32
// ===========================================================================
#define SMEM_F_GEN 22304

__global__ __launch_bounds__(256, 2)
void gnn_generic_kernel(const int* __restrict__ fp,
                        const float* __restrict__ emb,
                        const float* __restrict__ b_fp,
                        const float* __restrict__ b_out,
                        const float* __restrict__ wprop,
                        const float* __restrict__ bprop,
                        const int* __restrict__ esrc,
                        const int* __restrict__ edst,
                        float* __restrict__ out,
                        int S, int G, int M, int E, int LH, int LO) {
    extern __shared__ float sm[];
    float* A      = sm;
    float* H      = sm + 8192;
    float* Bw     = sm + 16384;
    float* bias_sh = sm + 20480;
    unsigned* cnt_sh = (unsigned*)(sm + 20992);
    int*      fpx_sh = (int*)(sm + 21120);
    unsigned char* slot_sh = (unsigned char*)(sm + 21248);
    unsigned char* mb_sh   = (unsigned char*)(sm + 22272);

    const int t = threadIdx.x;
    const int warp = t >> 5, lane = t & 31;
    const int molBase = blockIdx.x * G;
    const int Ga = min(G, M - molBase);
    if (Ga <= 0) return;
    const int GA = Ga * S;
    const int atomBase = molBase * S;

    const u32 vbase = smem_u32(A);
    const u32 bbase = smem_u32(Bw);
    const int mi = lane >> 3, li = lane & 7;
    const int rA = warp * 16 + ((mi & 1) << 3) + li;
    const int rB0 = ((mi >> 1) << 3) + li;
    const int qAofs = mi >> 1, qBofs = mi & 1;

    {
        const u64* gs = (const u64*)(g_slots + (size_t)atomBase * CAP);
        u64* ss = (u64*)slot_sh;
        const int nQ = (GA * CAP) >> 3;
        for (int i = t; i < nQ; i += 256) ss[i] = gs[i];
        for (int r = t; r < GA; r += 256) {
            cnt_sh[r] = g_cnt[atomBase + r];
            g_cnt[atomBase + r] = 0u;
            fpx_sh[r] = fp[atomBase + r] * 16;
        }
        for (int r = t; r < TILE_ROWS; r += 256)
            mb_sh[r] = (unsigned char)((r / S) * S);
        if (t < LH * 64) bias_sh[t] = b_fp[t];
        const float4* ws = (const float4*)g_W;
        float4* wd = (float4*)Bw;
        for (int i = t; i < 1024; i += 256) {
            int n = i >> 4, q = i & 15;
            wd[(n << 4) + (q ^ (n & 7))] = ws[i];
        }
    }
    __syncthreads();

    {
        const float4* eq = (const float4*)emb;
        for (int idx = t; idx < GA * 16; idx += 256) {
            int r = idx >> 4, q = idx & 15;
            float4 e = eq[fpx_sh[r] + q];
            e.x = cvtf_tf32(e.x); e.y = cvtf_tf32(e.y);
            e.z = cvtf_tf32(e.z); e.w = cvtf_tf32(e.w);
            *(float4*)&A[vadr(r, q, 0)] = e;
        }
        const float4 z = make_float4(0.f, 0.f, 0.f, 0.f);
        for (int idx = GA * 16 + t; idx < TILE_ROWS * 16; idx += 256)
            *(float4*)&A[vadr(idx >> 4, idx & 15, 0)] = z;
    }

    for (int l = 0; l < LH; l++) {
        __syncthreads();
        float C[8][4];
#pragma unroll
        for (int nt = 0; nt < 8; nt++)
#pragma unroll
            for (int i = 0; i < 4; i++) C[nt][i] = 0.f;
#pragma unroll
        for (int ks = 0; ks < 8; ks++) {
            u32 a0, a1, a2, a3;
            {
                u32 ad = vbase + 4u * (u32)vadr(rA, ks * 2 + qAofs, 0);
                LDSM_X4(a0, a1, a2, a3, ad);
            }
            u32 bfr[4][4];
#pragma unroll
            for (int g = 0; g < 4; g++) {
                u32 ad = bbase + 4u * (u32)vadr(g * 16 + rB0, ks * 2 + qBofs, 0);
                LDSM_X4(bfr[g][0], bfr[g][1], bfr[g][2], bfr[g][3], ad);
            }
#pragma unroll
            for (int nt = 0; nt < 8; nt++) {
                int g = nt >> 1, s2 = (nt & 1) * 2;
                MMA_TF32(C[nt], a0, a1, a2, a3, bfr[g][s2], bfr[g][s2 + 1]);
            }
        }
        {
            int er = warp * 16 + (lane >> 2);
            int ec = (lane & 3) * 2;
#pragma unroll
            for (int nt = 0; nt < 8; nt++) {
                int col = nt * 8 + ec;
                float2 bb = *(const float2*)&bias_sh[l * 64 + col];
                float2 h0, h1;
                h0.x = fmaxf(C[nt][0] + bb.x, 0.f);
                h0.y = fmaxf(C[nt][1] + bb.y, 0.f);
                h1.x = fmaxf(C[nt][2] + bb.x, 0.f);
                h1.y = fmaxf(C[nt][3] + bb.y, 0.f);
                *(float2*)&H[vadr(er,     col >> 2, col & 3)] = h0;
                *(float2*)&H[vadr(er + 8, col >> 2, col & 3)] = h1;
            }
        }
        __syncthreads();

        const bool lastL = (l == LH - 1);
        const int aq = lane >> 1, awo = (lane & 1) * 2, c2 = lane * 2;
        for (int r = warp; r < GA; r += 8) {
            unsigned c = cnt_sh[r];
            int mb = mb_sh[r];
            float2 a = *(const float2*)&H[vadr(r, aq, awo)];
            if (c <= CAP) {
                const unsigned char* sl = slot_sh + r * CAP;
                float2 s1 = make_float2(0.f, 0.f);
                unsigned e = 0;
                for (; e + 2 <= c; e += 2) {
                    int n0 = mb + sl[e], n1 = mb + sl[e + 1];
                    float2 h0 = *(const float2*)&H[vadr(n0, aq, awo)];
                    float2 h1 = *(const float2*)&H[vadr(n1, aq, awo)];
                    a.x += h0.x;  a.y += h0.y;
                    s1.x += h1.x; s1.y += h1.y;
                }
                if (e < c) {
                    int n0 = mb + sl[e];
                    float2 h0 = *(const float2*)&H[vadr(n0, aq, awo)];
                    a.x += h0.x; a.y += h0.y;
                }
                a.x += s1.x; a.y += s1.y;
            } else {
                a = gather_fallback(H, atomBase + r, mb, S, E, esrc, edst,
                                    aq, awo, a);
            }
            float ss = a.x * a.x + a.y * a.y;
#pragma unroll
            for (int o = 16; o; o >>= 1) ss += __shfl_xor_sync(0xffffffffu, ss, o);
            float iv = rsqrtf(fmaxf(ss, 1e-24f));
            a.x *= iv; a.y *= iv;
            if (!lastL) {
                float2 w1; w1.x = cvtf_tf32(a.x); w1.y = cvtf_tf32(a.y);
                *(float2*)&A[vadr(r, aq, awo)] = w1;
            } else {
                *(float2*)&A[r * 64 + c2] = a;
            }
        }
        if (l + 1 < LH) {
            const float4* ws = (const float4*)(g_W + (l + 1) * 4096);
            float4* wd = (float4*)Bw;
            for (int i = t; i < 1024; i += 256) {
                int n = i >> 4, q = i & 15;
                wd[(n << 4) + (q ^ (n & 7))] = ws[i];
            }
        } else {
            const float4* ws = (const float4*)g_Wt;
            float4* wd = (float4*)Bw;
            for (int i = t; i < 1024; i += 256) wd[i] = ws[i];
        }
    }
    __syncthreads();

    const int c2 = lane * 2;
    for (int m = warp; m < Ga; m += 8) {
        float2 s = make_float2(0.f, 0.f);
        for (int i = 0; i < S; i++) {
            float2 x = *(const float2*)&A[(m * S + i) * 64 + c2];
            s.x += x.x; s.y += x.y;
        }
        *(float2*)&H[m * 64 + c2] = s;
    }

    float* cur = H;
    float* nxt = A;
    for (int l = 0; l < LO; l++) {
        if (l > 0) {
            __syncthreads();
            const float4* ws = (const float4*)(g_Wt + l * 4096);
            float4* wd = (float4*)Bw;
            for (int i = t; i < 1024; i += 256) wd[i] = ws[i];
        }
        __syncthreads();
        for (int m = warp; m < Ga; m += 8) {
            float2 a = *(const float2*)&b_out[l * 64 + c2];
#pragma unroll 8
            for (int k = 0; k < 64; k++) {
                float cc = cur[m * 64 + k];
                float2 w2 = *(const float2*)&Bw[k * 64 + c2];
                a.x = fmaf(cc, w2.x, a.x); a.y = fmaf(cc, w2.y, a.y);
            }
            a.x = fmaxf(a.x, 0.f); a.y = fmaxf(a.y, 0.f);
            *(float2*)&nxt[m * 64 + c2] = a;
        }
        float* tmp = cur; cur = nxt; nxt = tmp;
    }
    __syncthreads();

    for (int m = warp; m < Ga; m += 8) {
        float s = cur[m * 64 + lane] * wprop[lane]
                + cur[m * 64 + 32 + lane] * wprop[32 + lane];
#pragma unroll
        for (int o = 16; o; o >>= 1) s += __shfl_xor_sync(0xffffffffu, s, o);
        if (lane == 0) out[molBase + m] = s + bprop[0];
    }
}

// ---------------------------------------------------------------------------

extern "C" void kernel_launch(void* const* d_in, const int* in_sizes, int n_in,
                              void* d_out, int out_size) {
    const float* emb    = (const float*)d_in[0];
    const float* W_fp   = (const float*)d_in[1];
    const float* b_fp   = (const float*)d_in[2];
    const float* W_out  = (const float*)d_in[3];
    const float* b_out  = (const float*)d_in[4];
    const float* W_prop = (const float*)d_in[5];
    const float* b_prop = (const float*)d_in[6];
    const int*   fp     = (const int*)d_in[7];
    const int*   esrc   = (const int*)d_in[8];
    const int*   edst   = (const int*)d_in[9];

    float* out = (float*)d_out;

    const int M  = out_size;
    const int T  = in_sizes[7];
    const int E  = in_sizes[8];
    const int LH = in_sizes[2] / 64;
    const int LO = in_sizes[4] / 64;
    const int S  = T / M;

    const int EB = (E + 255) / 256;
    prep_kernel<<<EB + LH + LO, 256>>>(esrc, edst, E, S, EB, W_fp, W_out, LH);

    if (S <= 32 && LH <= MAX_LAY && LO <= MAX_LAY) {
        const int smemBytes = SMEM_TC_F * 4;        // 109056 B
        cudaFuncSetAttribute(gnn_tc_kernel,
                             cudaFuncAttributeMaxDynamicSharedMemorySize, smemBytes);
        const int nBlocks = (M + MPC - 1) / MPC;
        gnn_tc_kernel<<<nBlocks, 256, smemBytes>>>(
            fp, emb, b_fp, b_out, W_prop, b_prop, esrc, edst, out,
            S, M, E, LH, LO);
    } else {
        int G = TILE_ROWS / S;
        if (G < 1) G = 1;
        const int smemBytes = SMEM_F_GEN * 4;
        cudaFuncSetAttribute(gnn_generic_kernel,
                             cudaFuncAttributeMaxDynamicSharedMemorySize, smemBytes);
        const int nBlocks = (M + G - 1) / G;
        gnn_generic_kernel<<<nBlocks, 256, smemBytes>>>(
            fp, emb, b_fp, b_out, W_prop, b_prop, esrc, edst, out,
            S, G, M, E, LH, LO);
    }
}

// round 17
// speedup vs baseline: 1.1095x; 1.0539x over previous
#include <cuda_runtime.h>
#include <math.h>
#include <cstdint>

// ---------------------------------------------------------------------------
// MolecularGNN fused, R16 = R13 (best) + 32x32 warp tiling of the layer GEMM:
//  warp w -> rows 32*(w>>1), cols 32*(w&1); per ks 2 A-ldsm + 2 B-ldsm
//  (was 1+4) -> layer-GEMM smem wavefronts -20%. Numerics bit-identical.
//  MLP tail reverted to exact R13 (R15's 8-warp tail was neutral).
// ---------------------------------------------------------------------------

#define MAX_T 524288
#define MAX_LAY 8
#define CAP 32
#define TILE_ROWS 128
#define MPC 4               // molecules per CTA (tensor path)

typedef unsigned long long u64;
typedef unsigned u32;

__device__ unsigned      g_cnt[MAX_T];                  // zero-init (.bss)
__device__ unsigned char g_slots[(size_t)MAX_T * CAP];
__device__ float         g_W [MAX_LAY * 4096];          // GNN W, tf32, [n][k]
__device__ float         g_Wt[MAX_LAY * 4096];          // MLP W, transposed

__device__ __forceinline__ u32 cvt_tf32(float f) {
    u32 u; asm("cvt.rna.tf32.f32 %0, %1;" : "=r"(u) : "f"(f)); return u;
}
__device__ __forceinline__ float cvtf_tf32(float f) {
    return __uint_as_float(cvt_tf32(f));
}
__device__ __forceinline__ int vadr(int r, int q, int wo) {
    return r * 64 + (((q ^ (r & 7)) << 2) + wo);
}
__device__ __forceinline__ u32 smem_u32(const void* p) {
    u32 a; asm("{ .reg .u64 t; cvta.to.shared.u64 t, %1; cvt.u32.u64 %0, t; }"
               : "=r"(a) : "l"(p));
    return a;
}
#define LDSM_X4(r0, r1, r2, r3, addr) \
    asm volatile("ldmatrix.sync.aligned.m8n8.x4.shared.b16 {%0,%1,%2,%3}, [%4];" \
                 : "=r"(r0), "=r"(r1), "=r"(r2), "=r"(r3) : "r"(addr))
#define MMA_TF32(c, a0, a1, a2, a3, b0, b1) \
    asm volatile("mma.sync.aligned.m16n8k8.row.col.f32.tf32.tf32.f32 " \
                 "{%0,%1,%2,%3},{%4,%5,%6,%7},{%8,%9},{%0,%1,%2,%3};" \
                 : "+f"((c)[0]), "+f"((c)[1]), "+f"((c)[2]), "+f"((c)[3]) \
                 : "r"(a0), "r"(a1), "r"(a2), "r"(a3), "r"(b0), "r"(b1))

// ---------------------------------------------------------------------------
__global__ void prep_kernel(const int* __restrict__ src,
                            const int* __restrict__ dst, int E, int S, int EB,
                            const float* __restrict__ Wfp,
                            const float* __restrict__ Wout, int LH) {
    int b = blockIdx.x;
    if (b < EB) {
        int e = b * 256 + threadIdx.x;
        if (e < E) {
            int d = dst[e];
            unsigned idx = atomicAdd(&g_cnt[d], 1u);
            if (idx < CAP) {
                int s = src[e];
                g_slots[(size_t)d * CAP + idx] = (unsigned char)(s - (s / S) * S);
            }
        }
    } else if (b < EB + LH) {
        int l = b - EB;
        const float* Ws = Wfp + l * 4096;
        float* o = g_W + l * 4096;
        for (int i = threadIdx.x; i < 4096; i += blockDim.x)
            o[i] = cvtf_tf32(Ws[i]);
    } else {
        int l = b - EB - LH;
        const float* Ws = Wout + l * 4096;
        float* o = g_Wt + l * 4096;
        for (int i = threadIdx.x; i < 4096; i += blockDim.x) {
            int k = i >> 6, j = i & 63;
            o[i] = Ws[j * 64 + k];
        }
    }
}

// rare-path fallback (degree > CAP), generic kernel only
__device__ __noinline__ float2 gather_fallback(const float* __restrict__ X,
                                               int n, int mb, int S, int E,
                                               const int* __restrict__ esrc,
                                               const int* __restrict__ edst,
                                               int aq, int awo, float2 a) {
    for (int e = 0; e < E; e++)
        if (edst[e] == n) {
            int s = esrc[e];
            int nr = mb + (s - (s / S) * S);
            float2 hh = *(const float2*)&X[vadr(nr, aq, awo)];
            a.x += hh.x; a.y += hh.y;
        }
    return a;
}

// ===========================================================================
// Tensor-agg kernel (S <= 32). smem floats:
//  X 0..8192 | HT 8192..16640 (64x132) | Bw 16640..20736 | Cm 20736..24832 |
//  bias 24832 | molA 25344 | molB 25664 | cnt 25984 | fpx 26112 |
//  slots 26240..27264 (4096B)      total 27264 f = 109056 B
// ===========================================================================
#define SMEM_TC_F 27264

__global__ __launch_bounds__(256, 2)
void gnn_tc_kernel(const int* __restrict__ fp,
                   const float* __restrict__ emb,
                   const float* __restrict__ b_fp,
                   const float* __restrict__ b_out,
                   const float* __restrict__ wprop,
                   const float* __restrict__ bprop,
                   const int* __restrict__ esrc,
                   const int* __restrict__ edst,
                   float* __restrict__ out,
                   int S, int M, int E, int LH, int LO) {
    extern __shared__ float sm[];
    float* X       = sm;
    float* HT      = sm + 8192;
    float* Bw      = sm + 16640;
    float* Cm      = sm + 20736;
    float* bias_sh = sm + 24832;
    float* molA    = sm + 25344;
    float* molB    = sm + 25664;
    unsigned* cnt_sh = (unsigned*)(sm + 25984);
    int*      fpx_sh = (int*)(sm + 26112);
    unsigned char* slot_sh = (unsigned char*)(sm + 26240);

    const int t = threadIdx.x;
    const int warp = t >> 5, lane = t & 31;
    const int molBase = blockIdx.x * MPC;
    const int Ga = min(MPC, M - molBase);
    if (Ga <= 0) return;
    const int atomBase = molBase * S;

    const u32 vbase = smem_u32(X);
    const u32 bbase = smem_u32(Bw);
    const u32 cbase = smem_u32(Cm);
    const u32 htbase = smem_u32(HT);

    const int mi = lane >> 3, li = lane & 7;
    const int rB0 = ((mi >> 1) << 3) + li;
    const int qAofs = mi >> 1, qBofs = mi & 1;
    const int aq = lane >> 1, awo = (lane & 1) * 2, c2 = lane * 2;
    // 32x32 layer-GEMM warp tiling
    const int wr = warp >> 1, wc = warp & 1;
    const int rAbase = wr * 32 + ((mi & 1) << 3) + li;   // + mt*16

    // ---- prologue: slots/cnt/fpx per padded row; bias; W(0) ----
    for (int r = t; r < TILE_ROWS; r += 256) {
        int m = r >> 5, d = r & 31;
        bool valid = (d < S) && (m < Ga);
        unsigned c = 0;
        if (valid) {
            int ga = atomBase + m * S + d;
            c = g_cnt[ga];
            g_cnt[ga] = 0u;
            fpx_sh[r] = fp[ga] * 16;
            const u64* gs = (const u64*)(g_slots + (size_t)ga * CAP);
            u64* ss = (u64*)(slot_sh + r * CAP);
            ss[0] = gs[0]; ss[1] = gs[1]; ss[2] = gs[2]; ss[3] = gs[3];
        }
        cnt_sh[r] = c;
    }
    if (t < LH * 64) bias_sh[t] = b_fp[t];
    {
        const float4* ws = (const float4*)g_W;
        float4* wd = (float4*)Bw;
        for (int i = t; i < 1024; i += 256) {
            int n = i >> 4, q = i & 15;
            wd[(n << 4) + (q ^ (n & 7))] = ws[i];
        }
    }
    __syncthreads();

    // ---- build C = I + counts (swizzled rows), one thread per row ----
    if (t < TILE_ROWS) {
        int m = t >> 5, d = t & 31;
        float* crow = Cm + m * 1024 + d * 32;
        for (int j = 0; j < 32; j++) crow[j] = 0.f;
        unsigned c = cnt_sh[t];
        if (c <= CAP) {
            const unsigned char* sl = slot_sh + t * CAP;
            for (unsigned e = 0; e < c; e++) {
                int s = sl[e];
                crow[(((s >> 2) ^ (d & 7)) << 2) + (s & 3)] += 1.f;
            }
        } else {                    // unreachable; correctness net
            int n = atomBase + m * S + d;
            for (int e = 0; e < E; e++)
                if (edst[e] == n) {
                    int sg = esrc[e];
                    int s = sg - (sg / S) * S;
                    crow[(((s >> 2) ^ (d & 7)) << 2) + (s & 3)] += 1.f;
                }
        }
        crow[(((d >> 2) ^ (d & 7)) << 2) + (d & 3)] += 1.f;    // +I
    }

    // ---- embeddings (tf32, swizzled; pad rows zero) ----
    {
        const float4* eq = (const float4*)emb;
        for (int idx = t; idx < TILE_ROWS * 16; idx += 256) {
            int r = idx >> 4, q = idx & 15;
            float4 e = make_float4(0.f, 0.f, 0.f, 0.f);
            if (((r & 31) < S) && ((r >> 5) < Ga)) {
                e = eq[fpx_sh[r] + q];
                e.x = cvtf_tf32(e.x); e.y = cvtf_tf32(e.y);
                e.z = cvtf_tf32(e.z); e.w = cvtf_tf32(e.w);
            }
            *(float4*)&X[vadr(r, q, 0)] = e;
        }
    }

    // ---- GNN layers ----
    for (int l = 0; l < LH; l++) {
        __syncthreads();            // X(v) + Bw(l) + Cm ready

        // layer GEMM: h = relu(v @ W^T + b), 32x32 per warp
        float C[2][4][4];
#pragma unroll
        for (int mt = 0; mt < 2; mt++)
#pragma unroll
            for (int nt = 0; nt < 4; nt++)
#pragma unroll
                for (int i = 0; i < 4; i++) C[mt][nt][i] = 0.f;
#pragma unroll
        for (int ks = 0; ks < 8; ks++) {
            u32 af[2][4];
#pragma unroll
            for (int mt = 0; mt < 2; mt++) {
                u32 ad = vbase + 4u * (u32)vadr(rAbase + mt * 16,
                                                ks * 2 + qAofs, 0);
                LDSM_X4(af[mt][0], af[mt][1], af[mt][2], af[mt][3], ad);
            }
            u32 bfr[2][4];
#pragma unroll
            for (int gg = 0; gg < 2; gg++) {
                int g = wc * 2 + gg;
                u32 ad = bbase + 4u * (u32)vadr(g * 16 + rB0,
                                                ks * 2 + qBofs, 0);
                LDSM_X4(bfr[gg][0], bfr[gg][1], bfr[gg][2], bfr[gg][3], ad);
            }
#pragma unroll
            for (int mt = 0; mt < 2; mt++)
#pragma unroll
                for (int nt = 0; nt < 4; nt++) {
                    int gg = nt >> 1, s2 = (nt & 1) * 2;
                    MMA_TF32(C[mt][nt], af[mt][0], af[mt][1], af[mt][2],
                             af[mt][3], bfr[gg][s2], bfr[gg][s2 + 1]);
                }
        }

        const bool lastL = (l == LH - 1);
        const int ec = (lane & 3) * 2;
        // epilogue -> H^T [col][atom], stride 132 (conflict-free), all layers
#pragma unroll
        for (int mt = 0; mt < 2; mt++) {
            int er = wr * 32 + mt * 16 + (lane >> 2);
#pragma unroll
            for (int nt = 0; nt < 4; nt++) {
                int col = wc * 32 + nt * 8 + ec;
                float2 bb = *(const float2*)&bias_sh[l * 64 + col];
                HT[col * 132 + er]           = fmaxf(C[mt][nt][0] + bb.x, 0.f);
                HT[(col + 1) * 132 + er]     = fmaxf(C[mt][nt][1] + bb.y, 0.f);
                HT[col * 132 + er + 8]       = fmaxf(C[mt][nt][2] + bb.x, 0.f);
                HT[(col + 1) * 132 + er + 8] = fmaxf(C[mt][nt][3] + bb.y, 0.f);
            }
        }
        __syncthreads();            // H^T ready

        if (warp < 4) {
            // agg GEMM: D[32,64] = C_m[32,32] @ H_m[32,64]  (mol = warp)
            const int m = warp;
            if (m < Ga) {
                float D[2][8][4];
#pragma unroll
                for (int mt = 0; mt < 2; mt++)
#pragma unroll
                    for (int nt = 0; nt < 8; nt++)
#pragma unroll
                        for (int i = 0; i < 4; i++) D[mt][nt][i] = 0.f;
#pragma unroll
                for (int ks = 0; ks < 4; ks++) {
                    u32 af[2][4];
#pragma unroll
                    for (int mt = 0; mt < 2; mt++) {
                        int row = mt * 16 + ((mi & 1) << 3) + li;
                        int q = ks * 2 + qAofs;
                        u32 ad = cbase + 4u * (u32)(m * 1024 + row * 32
                                   + ((q ^ (row & 7)) << 2));
                        LDSM_X4(af[mt][0], af[mt][1], af[mt][2], af[mt][3], ad);
                    }
                    u32 bf[4][4];
#pragma unroll
                    for (int g = 0; g < 4; g++) {
                        int n = g * 16 + rB0;
                        u32 ad = htbase + 4u * (u32)(n * 132 + m * 32
                                   + ks * 8 + qBofs * 4);
                        LDSM_X4(bf[g][0], bf[g][1], bf[g][2], bf[g][3], ad);
                    }
#pragma unroll
                    for (int mt = 0; mt < 2; mt++)
#pragma unroll
                        for (int nt = 0; nt < 8; nt++) {
                            int g = nt >> 1, s2 = (nt & 1) * 2;
                            MMA_TF32(D[mt][nt], af[mt][0], af[mt][1],
                                     af[mt][2], af[mt][3],
                                     bf[g][s2], bf[g][s2 + 1]);
                        }
                }
                // norm in-fragment + write v to X (swizzled)
                // interior layers: tf32-round for next MMA; last: full fp32
#pragma unroll
                for (int mt = 0; mt < 2; mt++)
#pragma unroll
                    for (int h = 0; h < 2; h++) {
                        float ssq = 0.f;
#pragma unroll
                        for (int nt = 0; nt < 8; nt++)
                            ssq += D[mt][nt][2 * h] * D[mt][nt][2 * h]
                                 + D[mt][nt][2 * h + 1] * D[mt][nt][2 * h + 1];
                        ssq += __shfl_xor_sync(0xffffffffu, ssq, 1);
                        ssq += __shfl_xor_sync(0xffffffffu, ssq, 2);
                        float iv = rsqrtf(fmaxf(ssq, 1e-24f));
                        int r = m * 32 + mt * 16 + h * 8 + (lane >> 2);
#pragma unroll
                        for (int nt = 0; nt < 8; nt++) {
                            int col = nt * 8 + ec;
                            float2 w;
                            if (!lastL) {
                                w.x = cvtf_tf32(D[mt][nt][2 * h] * iv);
                                w.y = cvtf_tf32(D[mt][nt][2 * h + 1] * iv);
                            } else {
                                w.x = D[mt][nt][2 * h] * iv;
                                w.y = D[mt][nt][2 * h + 1] * iv;
                            }
                            *(float2*)&X[vadr(r, col >> 2, col & 3)] = w;
                        }
                    }
            }
        } else {
            // warps 4-7: stage next weights
            if (!lastL) {           // next GNN layer (swizzled)
                const float4* ws = (const float4*)(g_W + (l + 1) * 4096);
                float4* wd = (float4*)Bw;
                for (int i = t - 128; i < 1024; i += 128) {
                    int n = i >> 4, q = i & 15;
                    wd[(n << 4) + (q ^ (n & 7))] = ws[i];
                }
            } else {                // MLP layer 0 (plain)
                const float4* ws = (const float4*)g_Wt;
                float4* wd = (float4*)Bw;
                for (int i = t - 128; i < 1024; i += 128) wd[i] = ws[i];
            }
        }
    }
    __syncthreads();    // X = v (swizzled fp32), Bw = MLP layer 0

    // ---- molecule sums (read swizzled) ----
    if (warp < Ga) {
        float2 s = make_float2(0.f, 0.f);
        for (int i = 0; i < S; i++) {
            float2 x = *(const float2*)&X[vadr(warp * 32 + i, aq, awo)];
            s.x += x.x; s.y += x.y;
        }
        *(float2*)&molA[warp * 64 + c2] = s;
    }
    __syncthreads();

    // ---- output MLP (warp per molecule) ----
    float* cur = molA;
    float* nxt = molB;
    for (int l = 0; l < LO; l++) {
        if (l > 0) {
            __syncthreads();
            const float4* ws = (const float4*)(g_Wt + l * 4096);
            float4* wd = (float4*)Bw;
            for (int i = t; i < 1024; i += 256) wd[i] = ws[i];
            __syncthreads();
        }
        if (warp < Ga) {
            float2 a = *(const float2*)&b_out[l * 64 + c2];
#pragma unroll 8
            for (int k = 0; k < 64; k++) {
                float cc = cur[warp * 64 + k];
                float2 w2 = *(const float2*)&Bw[k * 64 + c2];
                a.x = fmaf(cc, w2.x, a.x); a.y = fmaf(cc, w2.y, a.y);
            }
            a.x = fmaxf(a.x, 0.f); a.y = fmaxf(a.y, 0.f);
            *(float2*)&nxt[warp * 64 + c2] = a;
        }
        float* tmp = cur; cur = nxt; nxt = tmp;
        __syncthreads();
    }

    // ---- final dot ----
    if (warp < Ga) {
        float s = cur[warp * 64 + lane] * wprop[lane]
                + cur[warp * 64 + 32 + lane] * wprop[32 + lane];
#pragma unroll
        for (int o = 16; o; o >>= 1) s += __shfl_xor_sync(0xffffffffu, s, o);
        if (lane == 0) out[molBase + warp] = s + bprop[0];
    }
}

// ===========================================================================
// Generic fallback (R7 structure) for S > 32
// ===========================================================================
#define SMEM_F_GEN 22304

__global__ __launch_bounds__(256, 2)
void gnn_generic_kernel(const int* __restrict__ fp,
                        const float* __restrict__ emb,
                        const float* __restrict__ b_fp,
                        const float* __restrict__ b_out,
                        const float* __restrict__ wprop,
                        const float* __restrict__ bprop,
                        const int* __restrict__ esrc,
                        const int* __restrict__ edst,
                        float* __restrict__ out,
                        int S, int G, int M, int E, int LH, int LO) {
    extern __shared__ float sm[];
    float* A      = sm;
    float* H      = sm + 8192;
    float* Bw     = sm + 16384;
    float* bias_sh = sm + 20480;
    unsigned* cnt_sh = (unsigned*)(sm + 20992);
    int*      fpx_sh = (int*)(sm + 21120);
    unsigned char* slot_sh = (unsigned char*)(sm + 21248);
    unsigned char* mb_sh   = (unsigned char*)(sm + 22272);

    const int t = threadIdx.x;
    const int warp = t >> 5, lane = t & 31;
    const int molBase = blockIdx.x * G;
    const int Ga = min(G, M - molBase);
    if (Ga <= 0) return;
    const int GA = Ga * S;
    const int atomBase = molBase * S;

    const u32 vbase = smem_u32(A);
    const u32 bbase = smem_u32(Bw);
    const int mi = lane >> 3, li = lane & 7;
    const int rA = warp * 16 + ((mi & 1) << 3) + li;
    const int rB0 = ((mi >> 1) << 3) + li;
    const int qAofs = mi >> 1, qBofs = mi & 1;

    {
        const u64* gs = (const u64*)(g_slots + (size_t)atomBase * CAP);
        u64* ss = (u64*)slot_sh;
        const int nQ = (GA * CAP) >> 3;
        for (int i = t; i < nQ; i += 256) ss[i] = gs[i];
        for (int r = t; r < GA; r += 256) {
            cnt_sh[r] = g_cnt[atomBase + r];
            g_cnt[atomBase + r] = 0u;
            fpx_sh[r] = fp[atomBase + r] * 16;
        }
        for (int r = t; r < TILE_ROWS; r += 256)
            mb_sh[r] = (unsigned char)((r / S) * S);
        if (t < LH * 64) bias_sh[t] = b_fp[t];
        const float4* ws = (const float4*)g_W;
        float4* wd = (float4*)Bw;
        for (int i = t; i < 1024; i += 256) {
            int n = i >> 4, q = i & 15;
            wd[(n << 4) + (q ^ (n & 7))] = ws[i];
        }
    }
    __syncthreads();

    {
        const float4* eq = (const float4*)emb;
        for (int idx = t; idx < GA * 16; idx += 256) {
            int r = idx >> 4, q = idx & 15;
            float4 e = eq[fpx_sh[r] + q];
            e.x = cvtf_tf32(e.x); e.y = cvtf_tf32(e.y);
            e.z = cvtf_tf32(e.z); e.w = cvtf_tf32(e.w);
            *(float4*)&A[vadr(r, q, 0)] = e;
        }
        const float4 z = make_float4(0.f, 0.f, 0.f, 0.f);
        for (int idx = GA * 16 + t; idx < TILE_ROWS * 16; idx += 256)
            *(float4*)&A[vadr(idx >> 4, idx & 15, 0)] = z;
    }

    for (int l = 0; l < LH; l++) {
        __syncthreads();
        float C[8][4];
#pragma unroll
        for (int nt = 0; nt < 8; nt++)
#pragma unroll
            for (int i = 0; i < 4; i++) C[nt][i] = 0.f;
#pragma unroll
        for (int ks = 0; ks < 8; ks++) {
            u32 a0, a1, a2, a3;
            {
                u32 ad = vbase + 4u * (u32)vadr(rA, ks * 2 + qAofs, 0);
                LDSM_X4(a0, a1, a2, a3, ad);
            }
            u32 bfr[4][4];
#pragma unroll
            for (int g = 0; g < 4; g++) {
                u32 ad = bbase + 4u * (u32)vadr(g * 16 + rB0, ks * 2 + qBofs, 0);
                LDSM_X4(bfr[g][0], bfr[g][1], bfr[g][2], bfr[g][3], ad);
            }
#pragma unroll
            for (int nt = 0; nt < 8; nt++) {
                int g = nt >> 1, s2 = (nt & 1) * 2;
                MMA_TF32(C[nt], a0, a1, a2, a3, bfr[g][s2], bfr[g][s2 + 1]);
            }
        }
        {
            int er = warp * 16 + (lane >> 2);
            int ec = (lane & 3) * 2;
#pragma unroll
            for (int nt = 0; nt < 8; nt++) {
                int col = nt * 8 + ec;
                float2 bb = *(const float2*)&bias_sh[l * 64 + col];
                float2 h0, h1;
                h0.x = fmaxf(C[nt][0] + bb.x, 0.f);
                h0.y = fmaxf(C[nt][1] + bb.y, 0.f);
                h1.x = fmaxf(C[nt][2] + bb.x, 0.f);
                h1.y = fmaxf(C[nt][3] + bb.y, 0.f);
                *(float2*)&H[vadr(er,     col >> 2, col & 3)] = h0;
                *(float2*)&H[vadr(er + 8, col >> 2, col & 3)] = h1;
            }
        }
        __syncthreads();

        const bool lastL = (l == LH - 1);
        const int aq = lane >> 1, awo = (lane & 1) * 2, c2 = lane * 2;
        for (int r = warp; r < GA; r += 8) {
            unsigned c = cnt_sh[r];
            int mb = mb_sh[r];
            float2 a = *(const float2*)&H[vadr(r, aq, awo)];
            if (c <= CAP) {
                const unsigned char* sl = slot_sh + r * CAP;
                float2 s1 = make_float2(0.f, 0.f);
                unsigned e = 0;
                for (; e + 2 <= c; e += 2) {
                    int n0 = mb + sl[e], n1 = mb + sl[e + 1];
                    float2 h0 = *(const float2*)&H[vadr(n0, aq, awo)];
                    float2 h1 = *(const float2*)&H[vadr(n1, aq, awo)];
                    a.x += h0.x;  a.y += h0.y;
                    s1.x += h1.x; s1.y += h1.y;
                }
                if (e < c) {
                    int n0 = mb + sl[e];
                    float2 h0 = *(const float2*)&H[vadr(n0, aq, awo)];
                    a.x += h0.x; a.y += h0.y;
                }
                a.x += s1.x; a.y += s1.y;
            } else {
                a = gather_fallback(H, atomBase + r, mb, S, E, esrc, edst,
                                    aq, awo, a);
            }
            float ss = a.x * a.x + a.y * a.y;
#pragma unroll
            for (int o = 16; o; o >>= 1) ss += __shfl_xor_sync(0xffffffffu, ss, o);
            float iv = rsqrtf(fmaxf(ss, 1e-24f));
            a.x *= iv; a.y *= iv;
            if (!lastL) {
                float2 w1; w1.x = cvtf_tf32(a.x); w1.y = cvtf_tf32(a.y);
                *(float2*)&A[vadr(r, aq, awo)] = w1;
            } else {
                *(float2*)&A[r * 64 + c2] = a;
            }
        }
        if (l + 1 < LH) {
            const float4* ws = (const float4*)(g_W + (l + 1) * 4096);
            float4* wd = (float4*)Bw;
            for (int i = t; i < 1024; i += 256) {
                int n = i >> 4, q = i & 15;
                wd[(n << 4) + (q ^ (n & 7))] = ws[i];
            }
        } else {
            const float4* ws = (const float4*)g_Wt;
            float4* wd = (float4*)Bw;
            for (int i = t; i < 1024; i += 256) wd[i] = ws[i];
        }
    }
    __syncthreads();

    const int c2 = lane * 2;
    for (int m = warp; m < Ga; m += 8) {
        float2 s = make_float2(0.f, 0.f);
        for (int i = 0; i < S; i++) {
            float2 x = *(const float2*)&A[(m * S + i) * 64 + c2];
            s.x += x.x; s.y += x.y;
        }
        *(float2*)&H[m * 64 + c2] = s;
    }

    float* cur = H;
    float* nxt = A;
    for (int l = 0; l < LO; l++) {
        if (l > 0) {
            __syncthreads();
            const float4* ws = (const float4*)(g_Wt + l * 4096);
            float4* wd = (float4*)Bw;
            for (int i = t; i < 1024; i += 256) wd[i] = ws[i];
        }
        __syncthreads();
        for (int m = warp; m < Ga; m += 8) {
            float2 a = *(const float2*)&b_out[l * 64 + c2];
#pragma unroll 8
            for (int k = 0; k < 64; k++) {
                float cc = cur[m * 64 + k];
                float2 w2 = *(const float2*)&Bw[k * 64 + c2];
                a.x = fmaf(cc, w2.x, a.x); a.y = fmaf(cc, w2.y, a.y);
            }
            a.x = fmaxf(a.x, 0.f); a.y = fmaxf(a.y, 0.f);
            *(float2*)&nxt[m * 64 + c2] = a;
        }
        float* tmp = cur; cur = nxt; nxt = tmp;
    }
    __syncthreads();

    for (int m = warp; m < Ga; m += 8) {
        float s = cur[m * 64 + lane] * wprop[lane]
                + cur[m * 64 + 32 + lane] * wprop[32 + lane];
#pragma unroll
        for (int o = 16; o; o >>= 1) s += __shfl_xor_sync(0xffffffffu, s, o);
        if (lane == 0) out[molBase + m] = s + bprop[0];
    }
}

// ---------------------------------------------------------------------------

extern "C" void kernel_launch(void* const* d_in, const int* in_sizes, int n_in,
                              void* d_out, int out_size) {
    const float* emb    = (const float*)d_in[0];
    const float* W_fp   = (const float*)d_in[1];
    const float* b_fp   = (const float*)d_in[2];
    const float* W_out  = (const float*)d_in[3];
    const float* b_out  = (const float*)d_in[4];
    const float* W_prop = (const float*)d_in[5];
    const float* b_prop = (const float*)d_in[6];
    const int*   fp     = (const int*)d_in[7];
    const int*   esrc   = (const int*)d_in[8];
    const int*   edst   = (const int*)d_in[9];

    float* out = (float*)d_out;

    const int M  = out_size;
    const int T  = in_sizes[7];
    const int E  = in_sizes[8];
    const int LH = in_sizes[2] / 64;
    const int LO = in_sizes[4] / 64;
    const int S  = T / M;

    const int EB = (E + 255) / 256;
    prep_kernel<<<EB + LH + LO, 256>>>(esrc, edst, E, S, EB, W_fp, W_out, LH);

    if (S <= 32 && LH <= MAX_LAY && LO <= MAX_LAY) {
        const int smemBytes = SMEM_TC_F * 4;        // 109056 B
        cudaFuncSetAttribute(gnn_tc_kernel,
                             cudaFuncAttributeMaxDynamicSharedMemorySize, smemBytes);
        const int nBlocks = (M + MPC - 1) / MPC;
        gnn_tc_kernel<<<nBlocks, 256, smemBytes>>>(
            fp, emb, b_fp, b_out, W_prop, b_prop, esrc, edst, out,
            S, M, E, LH, LO);
    } else {
        int G = TILE_ROWS / S;
        if (G < 1) G = 1;
        const int smemBytes = SMEM_F_GEN * 4;
        cudaFuncSetAttribute(gnn_generic_kernel,
                             cudaFuncAttributeMaxDynamicSharedMemorySize, smemBytes);
        const int nBlocks = (M + G - 1) / G;
        gnn_generic_kernel<<<nBlocks, 256, smemBytes>>>(
            fp, emb, b_fp, b_out, W_prop, b_prop, esrc, edst, out,
            S, G, M, E, LH, LO);
    }
}